// round 6
// baseline (speedup 1.0000x reference)
#include <cuda_runtime.h>

// Problem-fixed maxima (N=100000 nodes, E=1600000 edges, IN=128, RANK=64, HID=128)
#define MAXN 100000
#define MAXE 1600000

// ---------------- scratch (static device globals; no allocation) ----------------
// Invariant: g_cnt is all-zero at entry of every kernel_launch call:
// zero at module load; scatter's atomicSub drains every counter back to 0 each call.
__device__ float g_h[MAXN * 64];      // h = x @ W
__device__ int   g_cnt[MAXN];         // in-degree histogram, then down-counting cursor
__device__ int   g_off[MAXN];         // block-local exclusive scan of counts
__device__ int   g_bsum[256];         // per-scan-block base offsets (exclusive)
__device__ int   g_ssrc[MAXE];        // src ids grouped by dst
__device__ float g_vt[64 * 128];      // V^T (row k, col j)

// ---------------- packed fp32x2 helpers (Blackwell FFMA2) ----------------
__device__ __forceinline__ unsigned long long ffma2(unsigned long long a,
                                                    unsigned long long b,
                                                    unsigned long long c) {
    unsigned long long d;
    asm("fma.rn.f32x2 %0, %1, %2, %3;" : "=l"(d) : "l"(a), "l"(b), "l"(c));
    return d;
}
__device__ __forceinline__ unsigned long long dup2(float v) {
    unsigned long long r;
    asm("mov.b64 %0, {%1, %1};" : "=l"(r) : "f"(v));
    return r;
}

// ---------------- GEMM1 body: h[256 rows] = x[256,128] @ W[128,64] ----------------
// 256 threads, 8x8 thread tile (rows: ty*4+ii + g*128; cols: tx*4 and 32+tx*4).
#define XS_STRIDE 36
__device__ __forceinline__ void gemm1_body(const float* __restrict__ x,
                                           const float* __restrict__ W,
                                           int n, int bid,
                                           float* xs /*256*36*/, float* ws /*32*64*/) {
    int tid = threadIdx.x;
    int ty = tid >> 3;          // 0..31
    int tx = tid & 7;           // 0..7
    int row0 = bid << 8;        // 256 rows per tile

    unsigned long long acc[8][4];
#pragma unroll
    for (int m = 0; m < 8; m++)
#pragma unroll
        for (int j = 0; j < 4; j++) acc[m][j] = 0ull;

    for (int k0 = 0; k0 < 128; k0 += 32) {
        __syncthreads();
        // xs[r][0..31], r = 0..255 (row-major, stride 36)
#pragma unroll
        for (int ii = 0; ii < 8; ii++) {
            int i = tid + ii * 256;          // 2048 float4
            int r = i >> 3, c4 = (i & 7) << 2;
            int gr = row0 + r;
            float4 v = (gr < n) ? *(const float4*)&x[gr * 128 + k0 + c4]
                                : make_float4(0.f, 0.f, 0.f, 0.f);
            *(float4*)&xs[r * XS_STRIDE + c4] = v;
        }
        // ws[k][0..63]
#pragma unroll
        for (int ii = 0; ii < 2; ii++) {
            int i = tid + ii * 256;          // 512 float4
            int k = i >> 4, c4 = (i & 15) << 2;
            *(float4*)&ws[k * 64 + c4] = *(const float4*)&W[(k0 + k) * 64 + c4];
        }
        __syncthreads();

#pragma unroll 2
        for (int k = 0; k < 32; k += 4) {
            float4 a4[8];
#pragma unroll
            for (int m = 0; m < 8; m++) {
                int r = ((m >> 2) << 7) + ty * 4 + (m & 3);
                a4[m] = *(float4*)&xs[r * XS_STRIDE + k];
            }
#pragma unroll
            for (int kk = 0; kk < 4; kk++) {
                ulonglong2 B0 = *(ulonglong2*)&ws[(k + kk) * 64 + tx * 4];
                ulonglong2 B1 = *(ulonglong2*)&ws[(k + kk) * 64 + 32 + tx * 4];
#pragma unroll
                for (int m = 0; m < 8; m++) {
                    unsigned long long av = dup2(((const float*)&a4[m])[kk]);
                    acc[m][0] = ffma2(av, B0.x, acc[m][0]);
                    acc[m][1] = ffma2(av, B0.y, acc[m][1]);
                    acc[m][2] = ffma2(av, B1.x, acc[m][2]);
                    acc[m][3] = ffma2(av, B1.y, acc[m][3]);
                }
            }
        }
    }
#pragma unroll
    for (int m = 0; m < 8; m++) {
        int gr = row0 + ((m >> 2) << 7) + ty * 4 + (m & 3);
        if (gr < n) {
            ulonglong2 o0; o0.x = acc[m][0]; o0.y = acc[m][1];
            ulonglong2 o1; o1.x = acc[m][2]; o1.y = acc[m][3];
            *(ulonglong2*)&g_h[gr * 64 + tx * 4]      = o0;
            *(ulonglong2*)&g_h[gr * 64 + 32 + tx * 4] = o1;
        }
    }
}

// ---------------- K1: gemm1 part A (blocks [0,gA)) + histogram ----------------
__global__ __launch_bounds__(256) void k1_gemm_hist(const float* __restrict__ x,
                                                    const float* __restrict__ W,
                                                    const int* __restrict__ dst,
                                                    int n, int e, int gA) {
    __shared__ float xs[256 * XS_STRIDE];
    __shared__ float ws[32 * 64];
    if ((int)blockIdx.x < gA) { gemm1_body(x, W, n, blockIdx.x, xs, ws); return; }
    int b = blockIdx.x - gA;
    int q = e >> 2;
    int i = b * 256 + threadIdx.x;
    if (i < q) {
        int4 d4 = ((const int4*)dst)[i];
        atomicAdd(&g_cnt[d4.x], 1);
        atomicAdd(&g_cnt[d4.y], 1);
        atomicAdd(&g_cnt[d4.z], 1);
        atomicAdd(&g_cnt[d4.w], 1);
    }
    if (b == 0 && threadIdx.x == 0)
        for (int j = q << 2; j < e; j++) atomicAdd(&g_cnt[dst[j]], 1);
}

// ---------------- scanA: block-local exclusive scan (warp-shfl, 1024 thr) ----------------
__global__ void k_scanA(int n) {
    int tid = threadIdx.x;
    int lane = tid & 31;
    int i = blockIdx.x * 1024 + tid;
    int v = (i < n) ? g_cnt[i] : 0;
    int s = v;
#pragma unroll
    for (int d = 1; d < 32; d <<= 1) {
        int u = __shfl_up_sync(0xffffffffu, s, d);
        if (lane >= d) s += u;
    }
    __shared__ int wsum[32];
    if (lane == 31) wsum[tid >> 5] = s;
    __syncthreads();
    if (tid < 32) {
        int t = wsum[tid];
        int ss = t;
#pragma unroll
        for (int d = 1; d < 32; d <<= 1) {
            int u = __shfl_up_sync(0xffffffffu, ss, d);
            if (lane >= d) ss += u;
        }
        wsum[tid] = ss;   // inclusive over warp totals
    }
    __syncthreads();
    int base = (tid >= 32) ? wsum[(tid >> 5) - 1] : 0;
    if (i < n) g_off[i] = base + s - v;
    if (tid == 1023) g_bsum[blockIdx.x] = base + s;   // block total
}

// ---------------- scanB (block 0) + V^T transpose (blocks 1..8) ----------------
__global__ void k_scanB_vt(const float* __restrict__ V, int nb) {
    if (blockIdx.x == 0) {
        int t = threadIdx.x;
        if (t >= 128) return;
        int lane = t & 31, w = t >> 5;
        int orig = (t < nb) ? g_bsum[t] : 0;
        int v = orig;
#pragma unroll
        for (int d = 1; d < 32; d <<= 1) {
            int u = __shfl_up_sync(0xffffffffu, v, d);
            if (lane >= d) v += u;
        }
        __shared__ int wsum[4];
        if (lane == 31) wsum[w] = v;
        __syncthreads();
        int add = 0;
#pragma unroll
        for (int k = 0; k < 4; k++) if (k < w) add += wsum[k];
        if (t < nb) g_bsum[t] = v - orig + add;   // exclusive prefix
        return;
    }
    // V^T: g_vt[k*128 + j] = V[j*64 + k]   (8192 elems, 8 blocks x 1024)
    int i0 = (blockIdx.x - 1) * 1024 + threadIdx.x;
#pragma unroll
    for (int j = 0; j < 4; j++) {
        int idx = i0 + j * 256;
        g_vt[idx] = V[(idx & 127) * 64 + (idx >> 7)];
    }
}

// ---------------- scatter one edge (g_cnt doubles as down-counter) ----------------
__device__ __forceinline__ void scatter_one(int s, int d) {
    int slot = atomicSub(&g_cnt[d], 1) - 1;
    g_ssrc[g_off[d] + g_bsum[d >> 10] + slot] = s;
}

// ---------------- K3: gemm1 part B (blocks [0,gB)) + scatter ----------------
__global__ __launch_bounds__(256) void k3_gemm_scatter(const float* __restrict__ x,
                                                       const float* __restrict__ W,
                                                       const int* __restrict__ src,
                                                       const int* __restrict__ dst,
                                                       int n, int e, int gA, int gB) {
    __shared__ float xs[256 * XS_STRIDE];
    __shared__ float ws[32 * 64];
    if ((int)blockIdx.x < gB) { gemm1_body(x, W, n, gA + blockIdx.x, xs, ws); return; }
    int b = blockIdx.x - gB;
    int q = e >> 2;
    int i = b * 256 + threadIdx.x;
    if (i < q) {
        int4 s4 = ((const int4*)src)[i];
        int4 d4 = ((const int4*)dst)[i];
        scatter_one(s4.x, d4.x);
        scatter_one(s4.y, d4.y);
        scatter_one(s4.z, d4.z);
        scatter_one(s4.w, d4.w);
    }
    if (b == 0 && threadIdx.x == 0)
        for (int j = q << 2; j < e; j++) scatter_one(src[j], dst[j]);
}

// ---------------- K4: fused segment-product aggregation + GEMM2 ----------------
// 128-row tile: ts[128][68] (agg result * norm), vs[64][132] (V^T copy),
// out tile = ts @ V^T : 128 rows x 128 cols, 8x8 thread tile.
#define TS_STRIDE 68
#define VS_STRIDE 132
#define K4_SMEM ((128 * TS_STRIDE + 64 * VS_STRIDE) * 4)
__global__ __launch_bounds__(256) void k4_agg_gemm2(const float* __restrict__ norm,
                                                    float* __restrict__ out,
                                                    int n, int e) {
    extern __shared__ float dyn[];
    float* ts = dyn;                       // [128][68]
    float* vs = dyn + 128 * TS_STRIDE;     // [64][132]
    int tid = threadIdx.x;
    int lane = tid & 31, wid = tid >> 5;
    int row0 = blockIdx.x << 7;            // 128 rows per tile

    // prefetch V^T into smem (coalesced float4 copy)
#pragma unroll
    for (int ii = 0; ii < 8; ii++) {
        int i = tid + ii * 256;            // 2048 float4
        int k = i >> 5, c4 = (i & 31) << 2;
        *(float4*)&vs[k * VS_STRIDE + c4] = *(const float4*)&g_vt[k * 128 + c4];
    }

    // --- aggregation: warp `wid` handles 16 consecutive rows ---
#pragma unroll 1
    for (int j = 0; j < 16; j++) {
        int r = wid * 16 + j;
        int v = row0 + r;
        float a0 = 0.f, a1 = 0.f;
        if (v < n) {
            a0 = 1.f; a1 = 1.f;
            int beg = g_off[v] + g_bsum[v >> 10];
            int end = (v + 1 < n) ? (g_off[v + 1] + g_bsum[(v + 1) >> 10]) : e;
            int i = beg;
            for (; i + 4 <= end; i += 4) {   // 8 outstanding 128B loads
                int s0 = g_ssrc[i], s1 = g_ssrc[i + 1];
                int s2 = g_ssrc[i + 2], s3 = g_ssrc[i + 3];
                float p0 = __ldg(&g_h[s0 * 64 + lane])      * __ldg(&g_h[s1 * 64 + lane]);
                float q0 = __ldg(&g_h[s0 * 64 + 32 + lane]) * __ldg(&g_h[s1 * 64 + 32 + lane]);
                float p1 = __ldg(&g_h[s2 * 64 + lane])      * __ldg(&g_h[s3 * 64 + lane]);
                float q1 = __ldg(&g_h[s2 * 64 + 32 + lane]) * __ldg(&g_h[s3 * 64 + 32 + lane]);
                a0 *= p0 * p1;
                a1 *= q0 * q1;
            }
            for (; i < end; i++) {
                int s = g_ssrc[i];
                a0 *= __ldg(&g_h[s * 64 + lane]);
                a1 *= __ldg(&g_h[s * 64 + 32 + lane]);
            }
            float nm = __ldg(&norm[v]);
            a0 *= nm; a1 *= nm;
        }
        ts[r * TS_STRIDE + lane]      = a0;
        ts[r * TS_STRIDE + 32 + lane] = a1;
    }
    __syncthreads();

    // --- GEMM2: out[128 rows][128 cols] = ts @ vs, 8x8 thread tile ---
    int ty = tid >> 4;   // 0..15 : rows ty*4+ii + g*64
    int tx = tid & 15;   // 0..15 : cols tx*4 and 64+tx*4
    unsigned long long acc[8][4];
#pragma unroll
    for (int m = 0; m < 8; m++)
#pragma unroll
        for (int j = 0; j < 4; j++) acc[m][j] = 0ull;

#pragma unroll 2
    for (int k = 0; k < 64; k += 4) {
        float4 a4[8];
#pragma unroll
        for (int m = 0; m < 8; m++) {
            int r = ((m >> 2) << 6) + ty * 4 + (m & 3);
            a4[m] = *(float4*)&ts[r * TS_STRIDE + k];
        }
#pragma unroll
        for (int kk = 0; kk < 4; kk++) {
            ulonglong2 B0 = *(ulonglong2*)&vs[(k + kk) * VS_STRIDE + tx * 4];
            ulonglong2 B1 = *(ulonglong2*)&vs[(k + kk) * VS_STRIDE + 64 + tx * 4];
#pragma unroll
            for (int m = 0; m < 8; m++) {
                unsigned long long av = dup2(((const float*)&a4[m])[kk]);
                acc[m][0] = ffma2(av, B0.x, acc[m][0]);
                acc[m][1] = ffma2(av, B0.y, acc[m][1]);
                acc[m][2] = ffma2(av, B1.x, acc[m][2]);
                acc[m][3] = ffma2(av, B1.y, acc[m][3]);
            }
        }
    }
#pragma unroll
    for (int m = 0; m < 8; m++) {
        int gr = row0 + ((m >> 2) << 6) + ty * 4 + (m & 3);
        if (gr < n) {
            ulonglong2 o0; o0.x = acc[m][0]; o0.y = acc[m][1];
            ulonglong2 o1; o1.x = acc[m][2]; o1.y = acc[m][3];
            *(ulonglong2*)&out[gr * 128 + tx * 4]      = o0;
            *(ulonglong2*)&out[gr * 128 + 64 + tx * 4] = o1;
        }
    }
}

// ---------------- launch ----------------
extern "C" void kernel_launch(void* const* d_in, const int* in_sizes, int n_in,
                              void* d_out, int out_size) {
    const float* x    = (const float*)d_in[0];
    const float* norm = (const float*)d_in[1];
    const float* W    = (const float*)d_in[2];
    const float* V    = (const float*)d_in[3];
    const int*   src  = (const int*)d_in[4];
    const int*   dst  = (const int*)d_in[5];
    float* out = (float*)d_out;

    int n = in_sizes[1];   // norm has N elements
    int e = in_sizes[4];   // src has E elements
    if (n <= 0) return;

    cudaFuncSetAttribute(k4_agg_gemm2,
                         cudaFuncAttributeMaxDynamicSharedMemorySize, K4_SMEM);

    int G1 = (n + 255) / 256;        // gemm1 blocks (256-row tiles)
    int gA = (G1 * 2) / 5;           // overlapped with histogram
    int gB = G1 - gA;                // overlapped with scatter
    int q  = e >> 2;
    int eb = (q + 255) / 256;        // edge blocks (4 edges/thread)
    if (eb < 1) eb = 1;
    int nb = (n + 1023) / 1024;      // scan blocks (<=128 required by scanB)

    k1_gemm_hist<<<gA + eb, 256>>>(x, W, dst, n, e, gA);
    k_scanA<<<nb, 1024>>>(n);
    k_scanB_vt<<<9, 256>>>(V, nb);
    k3_gemm_scatter<<<gB + eb, 256>>>(x, W, src, dst, n, e, gA, gB);
    k4_agg_gemm2<<<(n + 127) / 128, 256, K4_SMEM>>>(norm, out, n, e);
}

// round 7
// speedup vs baseline: 1.6741x; 1.6741x over previous
#include <cuda_runtime.h>

// Problem-fixed maxima (N=100000 nodes, E=1600000 edges, IN=128, RANK=64, HID=128)
#define MAXN 100000
#define MAXE 1600000

// ---------------- scratch (static device globals; no allocation) ----------------
// Invariant: g_cnt is all-zero at entry of every kernel_launch call:
// zero at module load; scatter's atomicSub drains every counter back to 0 each call.
__device__ float g_h[MAXN * 64];      // h = x @ W
__device__ int   g_cnt[MAXN];         // in-degree histogram, then down-counting cursor
__device__ int   g_off[MAXN];         // block-local exclusive scan of counts
__device__ int   g_bsum[256];         // per-scan-block base offsets (exclusive)
__device__ int   g_ssrc[MAXE];        // src ids grouped by dst
__device__ float g_vt[64 * 128];      // V^T (row k, col j)

// ---------------- packed fp32x2 helpers (Blackwell FFMA2) ----------------
__device__ __forceinline__ unsigned long long ffma2(unsigned long long a,
                                                    unsigned long long b,
                                                    unsigned long long c) {
    unsigned long long d;
    asm("fma.rn.f32x2 %0, %1, %2, %3;" : "=l"(d) : "l"(a), "l"(b), "l"(c));
    return d;
}
__device__ __forceinline__ unsigned long long dup2(float v) {
    unsigned long long r;
    asm("mov.b64 %0, {%1, %1};" : "=l"(r) : "f"(v));
    return r;
}

// ---------------- histogram (lean: 4 edges/thread) ----------------
__global__ void k_hist(const int* __restrict__ dst, int e) {
    int q = e >> 2;
    int i = blockIdx.x * blockDim.x + threadIdx.x;
    if (i < q) {
        int4 d4 = ((const int4*)dst)[i];
        atomicAdd(&g_cnt[d4.x], 1);
        atomicAdd(&g_cnt[d4.y], 1);
        atomicAdd(&g_cnt[d4.z], 1);
        atomicAdd(&g_cnt[d4.w], 1);
    }
    if (i == 0)
        for (int j = q << 2; j < e; j++) atomicAdd(&g_cnt[dst[j]], 1);
}

// ---------------- scanA: block-local exclusive scan (warp-shfl, 1024 thr) ----------------
__global__ void k_scanA(int n) {
    int tid = threadIdx.x;
    int lane = tid & 31;
    int i = blockIdx.x * 1024 + tid;
    int v = (i < n) ? g_cnt[i] : 0;
    int s = v;
#pragma unroll
    for (int d = 1; d < 32; d <<= 1) {
        int u = __shfl_up_sync(0xffffffffu, s, d);
        if (lane >= d) s += u;
    }
    __shared__ int wsum[32];
    if (lane == 31) wsum[tid >> 5] = s;
    __syncthreads();
    if (tid < 32) {
        int t = wsum[tid];
        int ss = t;
#pragma unroll
        for (int d = 1; d < 32; d <<= 1) {
            int u = __shfl_up_sync(0xffffffffu, ss, d);
            if (lane >= d) ss += u;
        }
        wsum[tid] = ss;   // inclusive over warp totals
    }
    __syncthreads();
    int base = (tid >= 32) ? wsum[(tid >> 5) - 1] : 0;
    if (i < n) g_off[i] = base + s - v;
    if (tid == 1023) g_bsum[blockIdx.x] = base + s;   // block total
}

// ---------------- scanB (block 0) + V^T transpose (blocks 1..8) ----------------
__global__ void k_scanB_vt(const float* __restrict__ V, int nb) {
    if (blockIdx.x == 0) {
        int t = threadIdx.x;
        if (t >= 128) return;
        int lane = t & 31, w = t >> 5;
        int orig = (t < nb) ? g_bsum[t] : 0;
        int v = orig;
#pragma unroll
        for (int d = 1; d < 32; d <<= 1) {
            int u = __shfl_up_sync(0xffffffffu, v, d);
            if (lane >= d) v += u;
        }
        __shared__ int wsum[4];
        if (lane == 31) wsum[w] = v;
        __syncthreads();
        int add = 0;
#pragma unroll
        for (int k = 0; k < 4; k++) if (k < w) add += wsum[k];
        if (t < nb) g_bsum[t] = v - orig + add;   // exclusive prefix
        return;
    }
    // V^T: g_vt[k*128 + j] = V[j*64 + k]   (8192 elems, 8 blocks x 256 x 4)
    int i0 = (blockIdx.x - 1) * 1024 + threadIdx.x;
#pragma unroll
    for (int j = 0; j < 4; j++) {
        int idx = i0 + j * 256;
        g_vt[idx] = V[(idx & 127) * 64 + (idx >> 7)];
    }
}

// ---------------- scatter (lean: 4 edges/thread; g_cnt as down-counter) ----------------
__device__ __forceinline__ void scatter_one(int s, int d) {
    int slot = atomicSub(&g_cnt[d], 1) - 1;
    g_ssrc[g_off[d] + g_bsum[d >> 10] + slot] = s;
}

__global__ void k_scatter(const int* __restrict__ src, const int* __restrict__ dst, int e) {
    int q = e >> 2;
    int i = blockIdx.x * blockDim.x + threadIdx.x;
    if (i < q) {
        int4 s4 = ((const int4*)src)[i];
        int4 d4 = ((const int4*)dst)[i];
        scatter_one(s4.x, d4.x);
        scatter_one(s4.y, d4.y);
        scatter_one(s4.z, d4.z);
        scatter_one(s4.w, d4.w);
    }
    if (i == 0)
        for (int j = q << 2; j < e; j++) scatter_one(src[j], dst[j]);
}

// ---------------- GEMM1: h[n,64] = x[n,128] @ W[128,64] ----------------
// 64-row tile, K chunked by 64, 256 threads, 4x4 register blocking, FFMA2 pairs.
__global__ __launch_bounds__(256) void k_gemm1(const float* __restrict__ x,
                                               const float* __restrict__ W, int n) {
    __shared__ float xs[64 * 68];
    __shared__ float ws[64 * 64];
    int tid = threadIdx.x;
    int ty = tid >> 4;
    int tx4 = (tid & 15) << 2;
    int row0 = blockIdx.x << 6;

    unsigned long long acc[4][2];
#pragma unroll
    for (int i = 0; i < 4; i++) { acc[i][0] = 0ull; acc[i][1] = 0ull; }

    for (int k0 = 0; k0 < 128; k0 += 64) {
        __syncthreads();
        for (int i = tid; i < 1024; i += 256) {
            int r = i >> 4, c = (i & 15) << 2;
            int gr = row0 + r;
            float4 v = (gr < n) ? *(const float4*)&x[gr * 128 + k0 + c]
                                : make_float4(0.f, 0.f, 0.f, 0.f);
            *(float4*)&xs[r * 68 + c] = v;
        }
        for (int i = tid; i < 1024; i += 256) {
            int k = i >> 4, c = (i & 15) << 2;
            *(float4*)&ws[k * 64 + c] = *(const float4*)&W[(k0 + k) * 64 + c];
        }
        __syncthreads();

#pragma unroll 4
        for (int k = 0; k < 64; k += 4) {
            float a[4][4];
#pragma unroll
            for (int i = 0; i < 4; i++)
                *(float4*)&a[i][0] = *(float4*)&xs[(ty * 4 + i) * 68 + k];
#pragma unroll
            for (int kk = 0; kk < 4; kk++) {
                ulonglong2 b = *(ulonglong2*)&ws[(k + kk) * 64 + tx4];
#pragma unroll
                for (int i = 0; i < 4; i++) {
                    unsigned long long av = dup2(a[i][kk]);
                    acc[i][0] = ffma2(av, b.x, acc[i][0]);
                    acc[i][1] = ffma2(av, b.y, acc[i][1]);
                }
            }
        }
    }
#pragma unroll
    for (int i = 0; i < 4; i++) {
        int gr = row0 + ty * 4 + i;
        if (gr < n) {
            ulonglong2 o; o.x = acc[i][0]; o.y = acc[i][1];
            *(ulonglong2*)&g_h[gr * 64 + tx4] = o;
        }
    }
}

// ---------------- K4: fused segment-product aggregation + GEMM2 ----------------
// 64-row tile: ts[64][68] (agg result * norm); out = ts @ V^T in two 64-col halves.
__global__ __launch_bounds__(256) void k4_agg_gemm2(const float* __restrict__ norm,
                                                    float* __restrict__ out,
                                                    int n, int e) {
    __shared__ float ts[64 * 68];
    __shared__ float vs[64 * 68];  // vs[k][j] = V^T[k][j0+j]
    int tid = threadIdx.x;
    int lane = tid & 31, wid = tid >> 5;
    int row0 = blockIdx.x << 6;

    // --- aggregation: warp `wid` handles 8 consecutive rows ---
#pragma unroll 1
    for (int j = 0; j < 8; j++) {
        int r = wid * 8 + j;
        int v = row0 + r;
        float a0 = 0.f, a1 = 0.f;
        if (v < n) {
            a0 = 1.f; a1 = 1.f;
            int beg = g_off[v] + g_bsum[v >> 10];
            int end = (v + 1 < n) ? (g_off[v + 1] + g_bsum[(v + 1) >> 10]) : e;
            int i = beg;
            for (; i + 4 <= end; i += 4) {   // 8 outstanding 128B loads
                int s0 = g_ssrc[i], s1 = g_ssrc[i + 1];
                int s2 = g_ssrc[i + 2], s3 = g_ssrc[i + 3];
                float p0 = __ldg(&g_h[s0 * 64 + lane])      * __ldg(&g_h[s1 * 64 + lane]);
                float q0 = __ldg(&g_h[s0 * 64 + 32 + lane]) * __ldg(&g_h[s1 * 64 + 32 + lane]);
                float p1 = __ldg(&g_h[s2 * 64 + lane])      * __ldg(&g_h[s3 * 64 + lane]);
                float q1 = __ldg(&g_h[s2 * 64 + 32 + lane]) * __ldg(&g_h[s3 * 64 + 32 + lane]);
                a0 *= p0 * p1;
                a1 *= q0 * q1;
            }
            for (; i < end; i++) {
                int s = g_ssrc[i];
                a0 *= __ldg(&g_h[s * 64 + lane]);
                a1 *= __ldg(&g_h[s * 64 + 32 + lane]);
            }
            float nm = __ldg(&norm[v]);
            a0 *= nm; a1 *= nm;
        }
        ts[r * 68 + lane]      = a0;
        ts[r * 68 + 32 + lane] = a1;
    }

    // --- GEMM2: out = ts @ V^T, two 64-col halves, 4x4 thread tile ---
    int ty = tid >> 4;
    int tx4 = (tid & 15) << 2;
    for (int half = 0; half < 2; half++) {
        int j0 = half << 6;
        __syncthreads();   // ts ready / previous half's compute done
        // coalesced float4 copy of V^T columns [j0, j0+64)
        for (int i = tid; i < 1024; i += 256) {
            int k = i >> 4, c4 = (i & 15) << 2;
            *(float4*)&vs[k * 68 + c4] = *(const float4*)&g_vt[k * 128 + j0 + c4];
        }
        __syncthreads();

        unsigned long long acc[4][2];
#pragma unroll
        for (int i = 0; i < 4; i++) { acc[i][0] = 0ull; acc[i][1] = 0ull; }

#pragma unroll 4
        for (int k = 0; k < 64; k += 4) {
            float a[4][4];
#pragma unroll
            for (int i = 0; i < 4; i++)
                *(float4*)&a[i][0] = *(float4*)&ts[(ty * 4 + i) * 68 + k];
#pragma unroll
            for (int kk = 0; kk < 4; kk++) {
                ulonglong2 b = *(ulonglong2*)&vs[(k + kk) * 68 + tx4];
#pragma unroll
                for (int i = 0; i < 4; i++) {
                    unsigned long long av = dup2(a[i][kk]);
                    acc[i][0] = ffma2(av, b.x, acc[i][0]);
                    acc[i][1] = ffma2(av, b.y, acc[i][1]);
                }
            }
        }
#pragma unroll
        for (int i = 0; i < 4; i++) {
            int gr = row0 + ty * 4 + i;
            if (gr < n) {
                ulonglong2 o; o.x = acc[i][0]; o.y = acc[i][1];
                *(ulonglong2*)&out[gr * 128 + j0 + tx4] = o;
            }
        }
    }
}

// ---------------- launch ----------------
extern "C" void kernel_launch(void* const* d_in, const int* in_sizes, int n_in,
                              void* d_out, int out_size) {
    const float* x    = (const float*)d_in[0];
    const float* norm = (const float*)d_in[1];
    const float* W    = (const float*)d_in[2];
    const float* V    = (const float*)d_in[3];
    const int*   src  = (const int*)d_in[4];
    const int*   dst  = (const int*)d_in[5];
    float* out = (float*)d_out;

    int n = in_sizes[1];   // norm has N elements
    int e = in_sizes[4];   // src has E elements
    if (n <= 0) return;

    int q  = e >> 2;
    int eb = (q + 255) / 256;        // edge blocks (4 edges/thread)
    if (eb < 1) eb = 1;
    int nb = (n + 1023) / 1024;      // scan blocks (<=128 required by scanB)
    int G  = (n + 63) / 64;          // 64-row tiles

    k_gemm1<<<G, 256>>>(x, W, n);
    k_hist<<<eb, 256>>>(dst, e);
    k_scanA<<<nb, 1024>>>(n);
    k_scanB_vt<<<9, 256>>>(V, nb);
    k_scatter<<<eb, 256>>>(src, dst, e);
    k4_agg_gemm2<<<G, 256>>>(norm, out, n, e);
}

// round 11
// speedup vs baseline: 1.7266x; 1.0313x over previous
#include <cuda_runtime.h>

// Problem-fixed maxima (N=100000 nodes, E=1600000 edges, IN=128, RANK=64, HID=128)
#define MAXN 100000
#define MAXE 1600000

// ---------------- scratch (static device globals; no allocation) ----------------
// Invariant: g_cnt is all-zero at entry of every kernel_launch call:
// zero at module load; scatter's atomicSub drains every counter back to 0 each call.
__device__ float g_h[MAXN * 64];      // h = x @ W
__device__ int   g_cnt[MAXN];         // in-degree histogram, then down-counting cursor
__device__ int   g_off[MAXN];         // block-local exclusive scan of counts
__device__ int   g_bsum[256];         // per-scan-block base offsets (exclusive)
__device__ int   g_ssrc[MAXE];        // src ids grouped by dst
__device__ float g_vt[64 * 128];      // V^T (row k, col j)

// ---------------- packed fp32x2 helpers (Blackwell FFMA2) ----------------
__device__ __forceinline__ unsigned long long ffma2(unsigned long long a,
                                                    unsigned long long b,
                                                    unsigned long long c) {
    unsigned long long d;
    asm("fma.rn.f32x2 %0, %1, %2, %3;" : "=l"(d) : "l"(a), "l"(b), "l"(c));
    return d;
}
__device__ __forceinline__ unsigned long long dup2(float v) {
    unsigned long long r;
    asm("mov.b64 %0, {%1, %1};" : "=l"(r) : "f"(v));
    return r;
}

// ---------------- GEMM1 body: h[64 rows] = x[64,128] @ W[128,64] ----------------
// 256 threads, 4x4 thread tile, FFMA2 pairs. Lean: ~52 regs.
__device__ __forceinline__ void gemm1_body(const float* __restrict__ x,
                                           const float* __restrict__ W,
                                           int n, int bid,
                                           float* xs /*64*68*/, float* ws /*64*64*/) {
    int tid = threadIdx.x;
    int ty = tid >> 4;
    int tx4 = (tid & 15) << 2;
    int row0 = bid << 6;

    unsigned long long acc[4][2];
#pragma unroll
    for (int i = 0; i < 4; i++) { acc[i][0] = 0ull; acc[i][1] = 0ull; }

    for (int k0 = 0; k0 < 128; k0 += 64) {
        __syncthreads();
        for (int i = tid; i < 1024; i += 256) {
            int r = i >> 4, c = (i & 15) << 2;
            int gr = row0 + r;
            float4 v = (gr < n) ? *(const float4*)&x[gr * 128 + k0 + c]
                                : make_float4(0.f, 0.f, 0.f, 0.f);
            *(float4*)&xs[r * 68 + c] = v;
        }
        for (int i = tid; i < 1024; i += 256) {
            int k = i >> 4, c = (i & 15) << 2;
            *(float4*)&ws[k * 64 + c] = *(const float4*)&W[(k0 + k) * 64 + c];
        }
        __syncthreads();

#pragma unroll 4
        for (int k = 0; k < 64; k += 4) {
            float a[4][4];
#pragma unroll
            for (int i = 0; i < 4; i++)
                *(float4*)&a[i][0] = *(float4*)&xs[(ty * 4 + i) * 68 + k];
#pragma unroll
            for (int kk = 0; kk < 4; kk++) {
                ulonglong2 b = *(ulonglong2*)&ws[(k + kk) * 64 + tx4];
#pragma unroll
                for (int i = 0; i < 4; i++) {
                    unsigned long long av = dup2(a[i][kk]);
                    acc[i][0] = ffma2(av, b.x, acc[i][0]);
                    acc[i][1] = ffma2(av, b.y, acc[i][1]);
                }
            }
        }
    }
#pragma unroll
    for (int i = 0; i < 4; i++) {
        int gr = row0 + ty * 4 + i;
        if (gr < n) {
            ulonglong2 o; o.x = acc[i][0]; o.y = acc[i][1];
            *(ulonglong2*)&g_h[gr * 64 + tx4] = o;
        }
    }
}

// ---------------- K1: gemm1 part A + histogram + V^T transpose ----------------
// Block roles: [0,gA) gemm; [gA, gA+eb) hist (4 edges/thread); [gA+eb, +8) V^T.
__global__ __launch_bounds__(256) void k1_gemm_hist_vt(const float* __restrict__ x,
                                                       const float* __restrict__ W,
                                                       const float* __restrict__ V,
                                                       const int* __restrict__ dst,
                                                       int n, int e, int gA, int eb) {
    __shared__ float xs[64 * 68];
    __shared__ float ws[64 * 64];
    int bid = blockIdx.x;
    if (bid < gA) { gemm1_body(x, W, n, bid, xs, ws); return; }
    if (bid < gA + eb) {
        int b = bid - gA;
        int q = e >> 2;
        int i = b * 256 + threadIdx.x;
        if (i < q) {
            int4 d4 = ((const int4*)dst)[i];
            atomicAdd(&g_cnt[d4.x], 1);
            atomicAdd(&g_cnt[d4.y], 1);
            atomicAdd(&g_cnt[d4.z], 1);
            atomicAdd(&g_cnt[d4.w], 1);
        }
        if (b == 0 && threadIdx.x == 0)
            for (int j = q << 2; j < e; j++) atomicAdd(&g_cnt[dst[j]], 1);
        return;
    }
    // V^T: g_vt[k*128 + j] = V[j*64 + k]   (8192 elems, 8 blocks x 256 x 4)
    int i0 = (bid - gA - eb) * 1024 + threadIdx.x;
#pragma unroll
    for (int j = 0; j < 4; j++) {
        int idx = i0 + j * 256;
        g_vt[idx] = V[(idx & 127) * 64 + (idx >> 7)];
    }
}

// ---------------- scanA: block-local exclusive scan (warp-shfl, 1024 thr) ----------------
__global__ void k_scanA(int n) {
    int tid = threadIdx.x;
    int lane = tid & 31;
    int i = blockIdx.x * 1024 + tid;
    int v = (i < n) ? g_cnt[i] : 0;
    int s = v;
#pragma unroll
    for (int d = 1; d < 32; d <<= 1) {
        int u = __shfl_up_sync(0xffffffffu, s, d);
        if (lane >= d) s += u;
    }
    __shared__ int wsum[32];
    if (lane == 31) wsum[tid >> 5] = s;
    __syncthreads();
    if (tid < 32) {
        int t = wsum[tid];
        int ss = t;
#pragma unroll
        for (int d = 1; d < 32; d <<= 1) {
            int u = __shfl_up_sync(0xffffffffu, ss, d);
            if (lane >= d) ss += u;
        }
        wsum[tid] = ss;   // inclusive over warp totals
    }
    __syncthreads();
    int base = (tid >= 32) ? wsum[(tid >> 5) - 1] : 0;
    if (i < n) g_off[i] = base + s - v;
    if (tid == 1023) g_bsum[blockIdx.x] = base + s;   // block total
}

// ---------------- scanB: parallel exclusive scan of <=128 block totals ----------------
__global__ void k_scanB(int nb) {
    int t = threadIdx.x;        // 128 threads
    int lane = t & 31, w = t >> 5;
    int orig = (t < nb) ? g_bsum[t] : 0;
    int v = orig;
#pragma unroll
    for (int d = 1; d < 32; d <<= 1) {
        int u = __shfl_up_sync(0xffffffffu, v, d);
        if (lane >= d) v += u;
    }
    __shared__ int wsum[4];
    if (lane == 31) wsum[w] = v;
    __syncthreads();
    int add = 0;
#pragma unroll
    for (int k = 0; k < 4; k++) if (k < w) add += wsum[k];
    if (t < nb) g_bsum[t] = v - orig + add;   // exclusive prefix
}

// ---------------- scatter one edge (g_cnt doubles as down-counter) ----------------
__device__ __forceinline__ void scatter_one(int s, int d) {
    int slot = atomicSub(&g_cnt[d], 1) - 1;
    g_ssrc[g_off[d] + g_bsum[d >> 10] + slot] = s;
}

// ---------------- K3: gemm1 part B (blocks [0,gB)) + scatter ----------------
__global__ __launch_bounds__(256) void k3_gemm_scatter(const float* __restrict__ x,
                                                       const float* __restrict__ W,
                                                       const int* __restrict__ src,
                                                       const int* __restrict__ dst,
                                                       int n, int e, int gA, int gB) {
    __shared__ float xs[64 * 68];
    __shared__ float ws[64 * 64];
    if ((int)blockIdx.x < gB) { gemm1_body(x, W, n, gA + blockIdx.x, xs, ws); return; }
    int b = blockIdx.x - gB;
    int q = e >> 2;
    int i = b * 256 + threadIdx.x;
    if (i < q) {
        int4 s4 = ((const int4*)src)[i];
        int4 d4 = ((const int4*)dst)[i];
        scatter_one(s4.x, d4.x);
        scatter_one(s4.y, d4.y);
        scatter_one(s4.z, d4.z);
        scatter_one(s4.w, d4.w);
    }
    if (b == 0 && threadIdx.x == 0)
        for (int j = q << 2; j < e; j++) scatter_one(src[j], dst[j]);
}

// ---------------- K4: fused segment-product aggregation + GEMM2 ----------------
// 64-row tile: ts[64][68] (agg result * norm); out = ts @ V^T in two 64-col halves.
__global__ __launch_bounds__(256) void k4_agg_gemm2(const float* __restrict__ norm,
                                                    float* __restrict__ out,
                                                    int n, int e) {
    __shared__ float ts[64 * 68];
    __shared__ float vs[64 * 68];  // vs[k][j] = V^T[k][j0+j]
    int tid = threadIdx.x;
    int lane = tid & 31, wid = tid >> 5;
    int row0 = blockIdx.x << 6;

    // --- aggregation: warp `wid` handles 8 consecutive rows ---
#pragma unroll 1
    for (int j = 0; j < 8; j++) {
        int r = wid * 8 + j;
        int v = row0 + r;
        float a0 = 0.f, a1 = 0.f;
        if (v < n) {
            a0 = 1.f; a1 = 1.f;
            int beg = g_off[v] + g_bsum[v >> 10];
            int end = (v + 1 < n) ? (g_off[v + 1] + g_bsum[(v + 1) >> 10]) : e;
            int i = beg;
            for (; i + 4 <= end; i += 4) {   // 8 outstanding 128B loads
                int s0 = g_ssrc[i], s1 = g_ssrc[i + 1];
                int s2 = g_ssrc[i + 2], s3 = g_ssrc[i + 3];
                float p0 = __ldg(&g_h[s0 * 64 + lane])      * __ldg(&g_h[s1 * 64 + lane]);
                float q0 = __ldg(&g_h[s0 * 64 + 32 + lane]) * __ldg(&g_h[s1 * 64 + 32 + lane]);
                float p1 = __ldg(&g_h[s2 * 64 + lane])      * __ldg(&g_h[s3 * 64 + lane]);
                float q1 = __ldg(&g_h[s2 * 64 + 32 + lane]) * __ldg(&g_h[s3 * 64 + 32 + lane]);
                a0 *= p0 * p1;
                a1 *= q0 * q1;
            }
            for (; i < end; i++) {
                int s = g_ssrc[i];
                a0 *= __ldg(&g_h[s * 64 + lane]);
                a1 *= __ldg(&g_h[s * 64 + 32 + lane]);
            }
            float nm = __ldg(&norm[v]);
            a0 *= nm; a1 *= nm;
        }
        ts[r * 68 + lane]      = a0;
        ts[r * 68 + 32 + lane] = a1;
    }

    // --- GEMM2: out = ts @ V^T, two 64-col halves, 4x4 thread tile ---
    int ty = tid >> 4;
    int tx4 = (tid & 15) << 2;
    for (int half = 0; half < 2; half++) {
        int j0 = half << 6;
        __syncthreads();   // ts ready / previous half's compute done
        // coalesced float4 copy of V^T columns [j0, j0+64)
        for (int i = tid; i < 1024; i += 256) {
            int k = i >> 4, c4 = (i & 15) << 2;
            *(float4*)&vs[k * 68 + c4] = *(const float4*)&g_vt[k * 128 + j0 + c4];
        }
        __syncthreads();

        unsigned long long acc[4][2];
#pragma unroll
        for (int i = 0; i < 4; i++) { acc[i][0] = 0ull; acc[i][1] = 0ull; }

#pragma unroll 4
        for (int k = 0; k < 64; k += 4) {
            float a[4][4];
#pragma unroll
            for (int i = 0; i < 4; i++)
                *(float4*)&a[i][0] = *(float4*)&ts[(ty * 4 + i) * 68 + k];
#pragma unroll
            for (int kk = 0; kk < 4; kk++) {
                ulonglong2 b = *(ulonglong2*)&vs[(k + kk) * 68 + tx4];
#pragma unroll
                for (int i = 0; i < 4; i++) {
                    unsigned long long av = dup2(a[i][kk]);
                    acc[i][0] = ffma2(av, b.x, acc[i][0]);
                    acc[i][1] = ffma2(av, b.y, acc[i][1]);
                }
            }
        }
#pragma unroll
        for (int i = 0; i < 4; i++) {
            int gr = row0 + ty * 4 + i;
            if (gr < n) {
                ulonglong2 o; o.x = acc[i][0]; o.y = acc[i][1];
                *(ulonglong2*)&out[gr * 128 + j0 + tx4] = o;
            }
        }
    }
}

// ---------------- launch ----------------
extern "C" void kernel_launch(void* const* d_in, const int* in_sizes, int n_in,
                              void* d_out, int out_size) {
    const float* x    = (const float*)d_in[0];
    const float* norm = (const float*)d_in[1];
    const float* W    = (const float*)d_in[2];
    const float* V    = (const float*)d_in[3];
    const int*   src  = (const int*)d_in[4];
    const int*   dst  = (const int*)d_in[5];
    float* out = (float*)d_out;

    int n = in_sizes[1];   // norm has N elements
    int e = in_sizes[4];   // src has E elements
    if (n <= 0) return;

    int G1 = (n + 63) / 64;          // gemm1 blocks (64-row tiles)
    int gA = (G1 * 2) / 5;           // overlapped with histogram
    int gB = G1 - gA;                // overlapped with scatter
    int q  = e >> 2;
    int eb = (q + 255) / 256;        // edge blocks (4 edges/thread)
    if (eb < 1) eb = 1;
    int nb = (n + 1023) / 1024;      // scan blocks (<=128 required by scanB)

    k1_gemm_hist_vt<<<gA + eb + 8, 256>>>(x, W, V, dst, n, e, gA, eb);
    k_scanA<<<nb, 1024>>>(n);
    k_scanB<<<1, 128>>>(nb);
    k3_gemm_scatter<<<gB + eb, 256>>>(x, W, src, dst, n, e, gA, gB);
    k4_agg_gemm2<<<G1, 256>>>(norm, out, n, e);
}

// round 13
// speedup vs baseline: 1.7659x; 1.0227x over previous
#include <cuda_runtime.h>

// Problem-fixed maxima (N=100000 nodes, E=1600000 edges, IN=128, HIDDEN=128, RANK=64)
#define MAXN 100000
#define MAXE 1600000

// ---------------- scratch (static device globals; no allocation) ----------------
// Invariant: g_cnt is all-zero at entry of every kernel_launch call:
// zero at module load; scatter's atomicSub drains every counter back to 0 each call.
__device__ float g_h[MAXN * 64];      // h = x @ W
__device__ int   g_cnt[MAXN];         // in-degree histogram, then down-counting cursor
__device__ int   g_off[MAXN];         // block-local exclusive scan of counts
__device__ int   g_bsum[256];         // per-scan-block base offsets (exclusive)
__device__ int   g_ssrc[MAXE];        // src ids grouped by dst
__device__ float g_vt[64 * 128];      // V^T (row k, col j)

// ---------------- packed fp32x2 helpers (Blackwell FFMA2 / FMUL2) ----------------
__device__ __forceinline__ unsigned long long ffma2(unsigned long long a,
                                                    unsigned long long b,
                                                    unsigned long long c) {
    unsigned long long d;
    asm("fma.rn.f32x2 %0, %1, %2, %3;" : "=l"(d) : "l"(a), "l"(b), "l"(c));
    return d;
}
__device__ __forceinline__ unsigned long long mul2(unsigned long long a,
                                                   unsigned long long b) {
    unsigned long long d;
    asm("mul.rn.f32x2 %0, %1, %2;" : "=l"(d) : "l"(a), "l"(b));
    return d;
}
__device__ __forceinline__ unsigned long long dup2(float v) {
    unsigned long long r;
    asm("mov.b64 %0, {%1, %1};" : "=l"(r) : "f"(v));
    return r;
}

// ---------------- GEMM1 body: h[64 rows] = x[64,128] @ W[128,64] ----------------
// 256 threads, 4x4 thread tile, FFMA2 pairs. Lean: ~52 regs.
__device__ __forceinline__ void gemm1_body(const float* __restrict__ x,
                                           const float* __restrict__ W,
                                           int n, int bid,
                                           float* xs /*64*68*/, float* ws /*64*64*/) {
    int tid = threadIdx.x;
    int ty = tid >> 4;
    int tx4 = (tid & 15) << 2;
    int row0 = bid << 6;

    unsigned long long acc[4][2];
#pragma unroll
    for (int i = 0; i < 4; i++) { acc[i][0] = 0ull; acc[i][1] = 0ull; }

    for (int k0 = 0; k0 < 128; k0 += 64) {
        __syncthreads();
        for (int i = tid; i < 1024; i += 256) {
            int r = i >> 4, c = (i & 15) << 2;
            int gr = row0 + r;
            float4 v = (gr < n) ? *(const float4*)&x[gr * 128 + k0 + c]
                                : make_float4(0.f, 0.f, 0.f, 0.f);
            *(float4*)&xs[r * 68 + c] = v;
        }
        for (int i = tid; i < 1024; i += 256) {
            int k = i >> 4, c = (i & 15) << 2;
            *(float4*)&ws[k * 64 + c] = *(const float4*)&W[(k0 + k) * 64 + c];
        }
        __syncthreads();

#pragma unroll 4
        for (int k = 0; k < 64; k += 4) {
            float a[4][4];
#pragma unroll
            for (int i = 0; i < 4; i++)
                *(float4*)&a[i][0] = *(float4*)&xs[(ty * 4 + i) * 68 + k];
#pragma unroll
            for (int kk = 0; kk < 4; kk++) {
                ulonglong2 b = *(ulonglong2*)&ws[(k + kk) * 64 + tx4];
#pragma unroll
                for (int i = 0; i < 4; i++) {
                    unsigned long long av = dup2(a[i][kk]);
                    acc[i][0] = ffma2(av, b.x, acc[i][0]);
                    acc[i][1] = ffma2(av, b.y, acc[i][1]);
                }
            }
        }
    }
#pragma unroll
    for (int i = 0; i < 4; i++) {
        int gr = row0 + ty * 4 + i;
        if (gr < n) {
            ulonglong2 o; o.x = acc[i][0]; o.y = acc[i][1];
            *(ulonglong2*)&g_h[gr * 64 + tx4] = o;
        }
    }
}

// ---------------- K1: gemm1 part A + histogram + V^T transpose ----------------
// Block roles: [0,gA) gemm; [gA, gA+eb) hist (4 edges/thread); [gA+eb, +8) V^T.
__global__ __launch_bounds__(256) void k1_gemm_hist_vt(const float* __restrict__ x,
                                                       const float* __restrict__ W,
                                                       const float* __restrict__ V,
                                                       const int* __restrict__ dst,
                                                       int n, int e, int gA, int eb) {
    __shared__ float xs[64 * 68];
    __shared__ float ws[64 * 64];
    int bid = blockIdx.x;
    if (bid < gA) { gemm1_body(x, W, n, bid, xs, ws); return; }
    if (bid < gA + eb) {
        int b = bid - gA;
        int q = e >> 2;
        int i = b * 256 + threadIdx.x;
        if (i < q) {
            int4 d4 = ((const int4*)dst)[i];
            atomicAdd(&g_cnt[d4.x], 1);
            atomicAdd(&g_cnt[d4.y], 1);
            atomicAdd(&g_cnt[d4.z], 1);
            atomicAdd(&g_cnt[d4.w], 1);
        }
        if (b == 0 && threadIdx.x == 0)
            for (int j = q << 2; j < e; j++) atomicAdd(&g_cnt[dst[j]], 1);
        return;
    }
    // V^T: g_vt[k*128 + j] = V[j*64 + k]   (8192 elems, 8 blocks x 256 x 4)
    int i0 = (bid - gA - eb) * 1024 + threadIdx.x;
#pragma unroll
    for (int j = 0; j < 4; j++) {
        int idx = i0 + j * 256;
        g_vt[idx] = V[(idx & 127) * 64 + (idx >> 7)];
    }
}

// ---------------- scanA: block-local exclusive scan (warp-shfl, 1024 thr) ----------------
__global__ void k_scanA(int n) {
    int tid = threadIdx.x;
    int lane = tid & 31;
    int i = blockIdx.x * 1024 + tid;
    int v = (i < n) ? g_cnt[i] : 0;
    int s = v;
#pragma unroll
    for (int d = 1; d < 32; d <<= 1) {
        int u = __shfl_up_sync(0xffffffffu, s, d);
        if (lane >= d) s += u;
    }
    __shared__ int wsum[32];
    if (lane == 31) wsum[tid >> 5] = s;
    __syncthreads();
    if (tid < 32) {
        int t = wsum[tid];
        int ss = t;
#pragma unroll
        for (int d = 1; d < 32; d <<= 1) {
            int u = __shfl_up_sync(0xffffffffu, ss, d);
            if (lane >= d) ss += u;
        }
        wsum[tid] = ss;   // inclusive over warp totals
    }
    __syncthreads();
    int base = (tid >= 32) ? wsum[(tid >> 5) - 1] : 0;
    if (i < n) g_off[i] = base + s - v;
    if (tid == 1023) g_bsum[blockIdx.x] = base + s;   // block total
}

// ---------------- scanB: parallel exclusive scan of <=128 block totals ----------------
__global__ void k_scanB(int nb) {
    int t = threadIdx.x;        // 128 threads
    int lane = t & 31, w = t >> 5;
    int orig = (t < nb) ? g_bsum[t] : 0;
    int v = orig;
#pragma unroll
    for (int d = 1; d < 32; d <<= 1) {
        int u = __shfl_up_sync(0xffffffffu, v, d);
        if (lane >= d) v += u;
    }
    __shared__ int wsum[4];
    if (lane == 31) wsum[w] = v;
    __syncthreads();
    int add = 0;
#pragma unroll
    for (int k = 0; k < 4; k++) if (k < w) add += wsum[k];
    if (t < nb) g_bsum[t] = v - orig + add;   // exclusive prefix
}

// ---------------- scatter one edge (g_cnt doubles as down-counter) ----------------
__device__ __forceinline__ void scatter_one(int s, int d) {
    int slot = atomicSub(&g_cnt[d], 1) - 1;
    g_ssrc[g_off[d] + g_bsum[d >> 10] + slot] = s;
}

// ---------------- K3: gemm1 part B (blocks [0,gB)) + scatter ----------------
__global__ __launch_bounds__(256) void k3_gemm_scatter(const float* __restrict__ x,
                                                       const float* __restrict__ W,
                                                       const int* __restrict__ src,
                                                       const int* __restrict__ dst,
                                                       int n, int e, int gA, int gB) {
    __shared__ float xs[64 * 68];
    __shared__ float ws[64 * 64];
    if ((int)blockIdx.x < gB) { gemm1_body(x, W, n, gA + blockIdx.x, xs, ws); return; }
    int b = blockIdx.x - gB;
    int q = e >> 2;
    int i = b * 256 + threadIdx.x;
    if (i < q) {
        int4 s4 = ((const int4*)src)[i];
        int4 d4 = ((const int4*)dst)[i];
        scatter_one(s4.x, d4.x);
        scatter_one(s4.y, d4.y);
        scatter_one(s4.z, d4.z);
        scatter_one(s4.w, d4.w);
    }
    if (b == 0 && threadIdx.x == 0)
        for (int j = q << 2; j < e; j++) scatter_one(src[j], dst[j]);
}

// ---------------- K4: fused segment-product aggregation + GEMM2 ----------------
// Aggregation gathers each 256B h-row with ONE warp-wide LDG.64 (lane l takes
// elements 2l, 2l+1) and multiplies with packed mul.rn.f32x2 — 8 LDG instr per
// 4 edges instead of 12, half the multiply instructions.
// ts layout identical to before (ts[r][c], c = 2*lane + {0,1}).
__global__ __launch_bounds__(256) void k4_agg_gemm2(const float* __restrict__ norm,
                                                    float* __restrict__ out,
                                                    int n, int e) {
    __shared__ float ts[64 * 68];
    __shared__ float vs[64 * 68];  // vs[k][j] = V^T[k][j0+j]
    int tid = threadIdx.x;
    int lane = tid & 31, wid = tid >> 5;
    int row0 = blockIdx.x << 6;

    // --- aggregation: warp `wid` handles 8 consecutive rows ---
#pragma unroll 1
    for (int j = 0; j < 8; j++) {
        int r = wid * 8 + j;
        int v = row0 + r;
        float rx = 0.f, ry = 0.f;
        if (v < n) {
            unsigned long long a = 0x3F8000003F800000ull;  // (1.0f, 1.0f)
            int beg = g_off[v] + g_bsum[v >> 10];
            int end = (v + 1 < n) ? (g_off[v + 1] + g_bsum[(v + 1) >> 10]) : e;
            int i = beg;
            for (; i + 4 <= end; i += 4) {   // 4 x 256B rows in flight
                int s0 = __ldg(&g_ssrc[i]),     s1 = __ldg(&g_ssrc[i + 1]);
                int s2 = __ldg(&g_ssrc[i + 2]), s3 = __ldg(&g_ssrc[i + 3]);
                unsigned long long v0 = __ldg((const unsigned long long*)&g_h[s0 * 64] + lane);
                unsigned long long v1 = __ldg((const unsigned long long*)&g_h[s1 * 64] + lane);
                unsigned long long v2 = __ldg((const unsigned long long*)&g_h[s2 * 64] + lane);
                unsigned long long v3 = __ldg((const unsigned long long*)&g_h[s3 * 64] + lane);
                a = mul2(a, mul2(mul2(v0, v1), mul2(v2, v3)));
            }
            for (; i < end; i++) {
                int s = __ldg(&g_ssrc[i]);
                a = mul2(a, __ldg((const unsigned long long*)&g_h[s * 64] + lane));
            }
            float nm = __ldg(&norm[v]);
            float2 f = *(float2*)&a;
            rx = f.x * nm;
            ry = f.y * nm;
        }
        *(float2*)&ts[r * 68 + 2 * lane] = make_float2(rx, ry);
    }

    // --- GEMM2: out = ts @ V^T, two 64-col halves, 4x4 thread tile ---
    int ty = tid >> 4;
    int tx4 = (tid & 15) << 2;
    for (int half = 0; half < 2; half++) {
        int j0 = half << 6;
        __syncthreads();   // ts ready / previous half's compute done
        // coalesced float4 copy of V^T columns [j0, j0+64)
        for (int i = tid; i < 1024; i += 256) {
            int k = i >> 4, c4 = (i & 15) << 2;
            *(float4*)&vs[k * 68 + c4] = *(const float4*)&g_vt[k * 128 + j0 + c4];
        }
        __syncthreads();

        unsigned long long acc[4][2];
#pragma unroll
        for (int i = 0; i < 4; i++) { acc[i][0] = 0ull; acc[i][1] = 0ull; }

#pragma unroll 4
        for (int k = 0; k < 64; k += 4) {
            float a[4][4];
#pragma unroll
            for (int i = 0; i < 4; i++)
                *(float4*)&a[i][0] = *(float4*)&ts[(ty * 4 + i) * 68 + k];
#pragma unroll
            for (int kk = 0; kk < 4; kk++) {
                ulonglong2 b = *(ulonglong2*)&vs[(k + kk) * 68 + tx4];
#pragma unroll
                for (int i = 0; i < 4; i++) {
                    unsigned long long av = dup2(a[i][kk]);
                    acc[i][0] = ffma2(av, b.x, acc[i][0]);
                    acc[i][1] = ffma2(av, b.y, acc[i][1]);
                }
            }
        }
#pragma unroll
        for (int i = 0; i < 4; i++) {
            int gr = row0 + ty * 4 + i;
            if (gr < n) {
                ulonglong2 o; o.x = acc[i][0]; o.y = acc[i][1];
                *(ulonglong2*)&out[gr * 128 + j0 + tx4] = o;
            }
        }
    }
}

// ---------------- launch ----------------
extern "C" void kernel_launch(void* const* d_in, const int* in_sizes, int n_in,
                              void* d_out, int out_size) {
    const float* x    = (const float*)d_in[0];
    const float* norm = (const float*)d_in[1];
    const float* W    = (const float*)d_in[2];
    const float* V    = (const float*)d_in[3];
    const int*   src  = (const int*)d_in[4];
    const int*   dst  = (const int*)d_in[5];
    float* out = (float*)d_out;

    int n = in_sizes[1];   // norm has N elements
    int e = in_sizes[4];   // src has E elements
    if (n <= 0) return;

    int G1 = (n + 63) / 64;          // gemm1 blocks (64-row tiles)
    int gA = (G1 * 2) / 5;           // overlapped with histogram
    int gB = G1 - gA;                // overlapped with scatter
    int q  = e >> 2;
    int eb = (q + 255) / 256;        // edge blocks (4 edges/thread)
    if (eb < 1) eb = 1;
    int nb = (n + 1023) / 1024;      // scan blocks (<=128 required by scanB)

    k1_gemm_hist_vt<<<gA + eb + 8, 256>>>(x, W, V, dst, n, e, gA, eb);
    k_scanA<<<nb, 1024>>>(n);
    k_scanB<<<1, 128>>>(nb);
    k3_gemm_scatter<<<gB + eb, 256>>>(x, W, src, dst, n, e, gA, gB);
    k4_agg_gemm2<<<G1, 256>>>(norm, out, n, e);
}

// round 15
// speedup vs baseline: 1.8912x; 1.0710x over previous
#include <cuda_runtime.h>

// Problem-fixed maxima (N=100000 nodes, E=1600000 edges, IN=128, HIDDEN=128, RANK=64)
#define MAXN 100000
#define MAXE 1600000

// ---------------- scratch (static device globals; no allocation) ----------------
// Invariants at entry of every kernel_launch call (static-init zero, self-restoring):
//  - g_cnt all-zero (scatter's atomicSub drains each counter to exactly 0)
//  - g_tick == 0   (last scan block resets it)
__device__ float g_h[MAXN * 64];      // h = x @ W
__device__ int   g_cnt[MAXN];         // in-degree histogram, then down-counting cursor
__device__ int   g_off[MAXN];         // block-local exclusive scan of counts
__device__ int   g_bsum[256];         // per-scan-block base offsets (exclusive)
__device__ int   g_ssrc[MAXE];        // src ids grouped by dst
__device__ float g_vt[64 * 128];      // V^T (row k, col j)
__device__ int   g_tick;              // scanAB completion ticket

// ---------------- packed fp32x2 helpers (Blackwell FFMA2 / FMUL2) ----------------
__device__ __forceinline__ unsigned long long ffma2(unsigned long long a,
                                                    unsigned long long b,
                                                    unsigned long long c) {
    unsigned long long d;
    asm("fma.rn.f32x2 %0, %1, %2, %3;" : "=l"(d) : "l"(a), "l"(b), "l"(c));
    return d;
}
__device__ __forceinline__ unsigned long long mul2(unsigned long long a,
                                                   unsigned long long b) {
    unsigned long long d;
    asm("mul.rn.f32x2 %0, %1, %2;" : "=l"(d) : "l"(a), "l"(b));
    return d;
}
__device__ __forceinline__ unsigned long long dup2(float v) {
    unsigned long long r;
    asm("mov.b64 %0, {%1, %1};" : "=l"(r) : "f"(v));
    return r;
}

// ---------------- GEMM1 body: h[64 rows] = x[64,128] @ W[128,64] ----------------
// 256 threads, 4x4 thread tile, FFMA2 pairs. Lean: ~52 regs.
__device__ __forceinline__ void gemm1_body(const float* __restrict__ x,
                                           const float* __restrict__ W,
                                           int n, int bid,
                                           float* xs /*64*68*/, float* ws /*64*64*/) {
    int tid = threadIdx.x;
    int ty = tid >> 4;
    int tx4 = (tid & 15) << 2;
    int row0 = bid << 6;

    unsigned long long acc[4][2];
#pragma unroll
    for (int i = 0; i < 4; i++) { acc[i][0] = 0ull; acc[i][1] = 0ull; }

    for (int k0 = 0; k0 < 128; k0 += 64) {
        __syncthreads();
        for (int i = tid; i < 1024; i += 256) {
            int r = i >> 4, c = (i & 15) << 2;
            int gr = row0 + r;
            float4 v = (gr < n) ? *(const float4*)&x[gr * 128 + k0 + c]
                                : make_float4(0.f, 0.f, 0.f, 0.f);
            *(float4*)&xs[r * 68 + c] = v;
        }
        for (int i = tid; i < 1024; i += 256) {
            int k = i >> 4, c = (i & 15) << 2;
            *(float4*)&ws[k * 64 + c] = *(const float4*)&W[(k0 + k) * 64 + c];
        }
        __syncthreads();

#pragma unroll 4
        for (int k = 0; k < 64; k += 4) {
            float a[4][4];
#pragma unroll
            for (int i = 0; i < 4; i++)
                *(float4*)&a[i][0] = *(float4*)&xs[(ty * 4 + i) * 68 + k];
#pragma unroll
            for (int kk = 0; kk < 4; kk++) {
                ulonglong2 b = *(ulonglong2*)&ws[(k + kk) * 64 + tx4];
#pragma unroll
                for (int i = 0; i < 4; i++) {
                    unsigned long long av = dup2(a[i][kk]);
                    acc[i][0] = ffma2(av, b.x, acc[i][0]);
                    acc[i][1] = ffma2(av, b.y, acc[i][1]);
                }
            }
        }
    }
#pragma unroll
    for (int i = 0; i < 4; i++) {
        int gr = row0 + ty * 4 + i;
        if (gr < n) {
            ulonglong2 o; o.x = acc[i][0]; o.y = acc[i][1];
            *(ulonglong2*)&g_h[gr * 64 + tx4] = o;
        }
    }
}

// ---------------- K1: FULL gemm1 + histogram + V^T transpose ----------------
// Block roles: [0,G1) gemm; [G1, G1+eb) hist (4 edges/thread); [G1+eb, +8) V^T.
__global__ __launch_bounds__(256) void k1_gemm_hist_vt(const float* __restrict__ x,
                                                       const float* __restrict__ W,
                                                       const float* __restrict__ V,
                                                       const int* __restrict__ dst,
                                                       int n, int e, int G1, int eb) {
    __shared__ float xs[64 * 68];
    __shared__ float ws[64 * 64];
    int bid = blockIdx.x;
    if (bid < G1) { gemm1_body(x, W, n, bid, xs, ws); return; }
    if (bid < G1 + eb) {
        int b = bid - G1;
        int q = e >> 2;
        int i = b * 256 + threadIdx.x;
        if (i < q) {
            int4 d4 = ((const int4*)dst)[i];
            atomicAdd(&g_cnt[d4.x], 1);
            atomicAdd(&g_cnt[d4.y], 1);
            atomicAdd(&g_cnt[d4.z], 1);
            atomicAdd(&g_cnt[d4.w], 1);
        }
        if (b == 0 && threadIdx.x == 0)
            for (int j = q << 2; j < e; j++) atomicAdd(&g_cnt[dst[j]], 1);
        return;
    }
    // V^T: g_vt[k*128 + j] = V[j*64 + k]   (8192 elems, 8 blocks x 256 x 4)
    int i0 = (bid - G1 - eb) * 1024 + threadIdx.x;
#pragma unroll
    for (int j = 0; j < 4; j++) {
        int idx = i0 + j * 256;
        g_vt[idx] = V[(idx & 127) * 64 + (idx >> 7)];
    }
}

// ---------------- scanAB: single-pass scan (block-local + last-block top scan) ----------------
__global__ void k_scanAB(int n, int nb) {
    int tid = threadIdx.x;
    int lane = tid & 31;
    int i = blockIdx.x * 1024 + tid;
    int v = (i < n) ? g_cnt[i] : 0;
    int s = v;
#pragma unroll
    for (int d = 1; d < 32; d <<= 1) {
        int u = __shfl_up_sync(0xffffffffu, s, d);
        if (lane >= d) s += u;
    }
    __shared__ int wsum[32];
    if (lane == 31) wsum[tid >> 5] = s;
    __syncthreads();
    if (tid < 32) {
        int t = wsum[tid];
        int ss = t;
#pragma unroll
        for (int d = 1; d < 32; d <<= 1) {
            int u = __shfl_up_sync(0xffffffffu, ss, d);
            if (lane >= d) ss += u;
        }
        wsum[tid] = ss;   // inclusive over warp totals
    }
    __syncthreads();
    int base = (tid >= 32) ? wsum[(tid >> 5) - 1] : 0;
    if (i < n) g_off[i] = base + s - v;
    if (tid == 1023) g_bsum[blockIdx.x] = base + s;   // block total

    // ---- last block scans the <=128 block totals (exclusive) ----
    __threadfence();
    __shared__ int lastflag;
    if (tid == 0) lastflag = (atomicAdd(&g_tick, 1) == nb - 1) ? 1 : 0;
    __syncthreads();
    if (!lastflag) return;

    __shared__ int wsum2[4];
    int t = tid;
    int orig = 0, vv = 0;
    if (t < 128) {
        orig = (t < nb) ? ((volatile int*)g_bsum)[t] : 0;
        vv = orig;
#pragma unroll
        for (int d = 1; d < 32; d <<= 1) {
            int u = __shfl_up_sync(0xffffffffu, vv, d);
            if (lane >= d) vv += u;
        }
        if (lane == 31) wsum2[t >> 5] = vv;
    }
    __syncthreads();
    if (t < 128) {
        int w = t >> 5;
        int add = 0;
#pragma unroll
        for (int k = 0; k < 4; k++) if (k < w) add += wsum2[k];
        if (t < nb) g_bsum[t] = vv - orig + add;   // exclusive prefix
    }
    if (t == 0) g_tick = 0;   // restore invariant for next call/replay
}

// ---------------- K3: lean scatter (4 edges/thread; g_cnt as down-counter) ----------------
__device__ __forceinline__ void scatter_one(int s, int d) {
    int slot = atomicSub(&g_cnt[d], 1) - 1;
    g_ssrc[g_off[d] + g_bsum[d >> 10] + slot] = s;
}

__global__ void k_scatter(const int* __restrict__ src, const int* __restrict__ dst, int e) {
    int q = e >> 2;
    int i = blockIdx.x * blockDim.x + threadIdx.x;
    if (i < q) {
        int4 s4 = ((const int4*)src)[i];
        int4 d4 = ((const int4*)dst)[i];
        scatter_one(s4.x, d4.x);
        scatter_one(s4.y, d4.y);
        scatter_one(s4.z, d4.z);
        scatter_one(s4.w, d4.w);
    }
    if (i == 0)
        for (int j = q << 2; j < e; j++) scatter_one(src[j], dst[j]);
}

// ---------------- K4: fused segment-product aggregation + GEMM2 ----------------
// Gather: warp-wide LDG.64 per 256B h-row (lane l -> elements 2l,2l+1),
// 8 rows in flight per iteration, packed mul.rn.f32x2 products.
__global__ __launch_bounds__(256) void k4_agg_gemm2(const float* __restrict__ norm,
                                                    float* __restrict__ out,
                                                    int n, int e) {
    __shared__ float ts[64 * 68];
    __shared__ float vs[64 * 68];  // vs[k][j] = V^T[k][j0+j]
    int tid = threadIdx.x;
    int lane = tid & 31, wid = tid >> 5;
    int row0 = blockIdx.x << 6;

    // --- aggregation: warp `wid` handles 8 consecutive rows ---
#pragma unroll 1
    for (int j = 0; j < 8; j++) {
        int r = wid * 8 + j;
        int v = row0 + r;
        float rx = 0.f, ry = 0.f;
        if (v < n) {
            unsigned long long a = 0x3F8000003F800000ull;  // (1.0f, 1.0f)
            int beg = g_off[v] + g_bsum[v >> 10];
            int end = (v + 1 < n) ? (g_off[v + 1] + g_bsum[(v + 1) >> 10]) : e;
            int i = beg;
            for (; i + 8 <= end; i += 8) {   // 8 x 256B rows in flight
                int s0 = __ldg(&g_ssrc[i]),     s1 = __ldg(&g_ssrc[i + 1]);
                int s2 = __ldg(&g_ssrc[i + 2]), s3 = __ldg(&g_ssrc[i + 3]);
                int s4 = __ldg(&g_ssrc[i + 4]), s5 = __ldg(&g_ssrc[i + 5]);
                int s6 = __ldg(&g_ssrc[i + 6]), s7 = __ldg(&g_ssrc[i + 7]);
                unsigned long long v0 = __ldg((const unsigned long long*)&g_h[s0 * 64] + lane);
                unsigned long long v1 = __ldg((const unsigned long long*)&g_h[s1 * 64] + lane);
                unsigned long long v2 = __ldg((const unsigned long long*)&g_h[s2 * 64] + lane);
                unsigned long long v3 = __ldg((const unsigned long long*)&g_h[s3 * 64] + lane);
                unsigned long long v4 = __ldg((const unsigned long long*)&g_h[s4 * 64] + lane);
                unsigned long long v5 = __ldg((const unsigned long long*)&g_h[s5 * 64] + lane);
                unsigned long long v6 = __ldg((const unsigned long long*)&g_h[s6 * 64] + lane);
                unsigned long long v7 = __ldg((const unsigned long long*)&g_h[s7 * 64] + lane);
                unsigned long long p01 = mul2(v0, v1), p23 = mul2(v2, v3);
                unsigned long long p45 = mul2(v4, v5), p67 = mul2(v6, v7);
                a = mul2(a, mul2(mul2(p01, p23), mul2(p45, p67)));
            }
            for (; i + 4 <= end; i += 4) {
                int s0 = __ldg(&g_ssrc[i]),     s1 = __ldg(&g_ssrc[i + 1]);
                int s2 = __ldg(&g_ssrc[i + 2]), s3 = __ldg(&g_ssrc[i + 3]);
                unsigned long long v0 = __ldg((const unsigned long long*)&g_h[s0 * 64] + lane);
                unsigned long long v1 = __ldg((const unsigned long long*)&g_h[s1 * 64] + lane);
                unsigned long long v2 = __ldg((const unsigned long long*)&g_h[s2 * 64] + lane);
                unsigned long long v3 = __ldg((const unsigned long long*)&g_h[s3 * 64] + lane);
                a = mul2(a, mul2(mul2(v0, v1), mul2(v2, v3)));
            }
            for (; i < end; i++) {
                int s = __ldg(&g_ssrc[i]);
                a = mul2(a, __ldg((const unsigned long long*)&g_h[s * 64] + lane));
            }
            float nm = __ldg(&norm[v]);
            float2 f = *(float2*)&a;
            rx = f.x * nm;
            ry = f.y * nm;
        }
        *(float2*)&ts[r * 68 + 2 * lane] = make_float2(rx, ry);
    }

    // --- GEMM2: out = ts @ V^T, two 64-col halves, 4x4 thread tile ---
    int ty = tid >> 4;
    int tx4 = (tid & 15) << 2;
    for (int half = 0; half < 2; half++) {
        int j0 = half << 6;
        __syncthreads();   // ts ready / previous half's compute done
        // coalesced float4 copy of V^T columns [j0, j0+64)
        for (int i = tid; i < 1024; i += 256) {
            int k = i >> 4, c4 = (i & 15) << 2;
            *(float4*)&vs[k * 68 + c4] = *(const float4*)&g_vt[k * 128 + j0 + c4];
        }
        __syncthreads();

        unsigned long long acc[4][2];
#pragma unroll
        for (int i = 0; i < 4; i++) { acc[i][0] = 0ull; acc[i][1] = 0ull; }

#pragma unroll 4
        for (int k = 0; k < 64; k += 4) {
            float a[4][4];
#pragma unroll
            for (int i = 0; i < 4; i++)
                *(float4*)&a[i][0] = *(float4*)&ts[(ty * 4 + i) * 68 + k];
#pragma unroll
            for (int kk = 0; kk < 4; kk++) {
                ulonglong2 b = *(ulonglong2*)&vs[(k + kk) * 68 + tx4];
#pragma unroll
                for (int i = 0; i < 4; i++) {
                    unsigned long long av = dup2(a[i][kk]);
                    acc[i][0] = ffma2(av, b.x, acc[i][0]);
                    acc[i][1] = ffma2(av, b.y, acc[i][1]);
                }
            }
        }
#pragma unroll
        for (int i = 0; i < 4; i++) {
            int gr = row0 + ty * 4 + i;
            if (gr < n) {
                ulonglong2 o; o.x = acc[i][0]; o.y = acc[i][1];
                *(ulonglong2*)&out[gr * 128 + j0 + tx4] = o;
            }
        }
    }
}

// ---------------- launch ----------------
extern "C" void kernel_launch(void* const* d_in, const int* in_sizes, int n_in,
                              void* d_out, int out_size) {
    const float* x    = (const float*)d_in[0];
    const float* norm = (const float*)d_in[1];
    const float* W    = (const float*)d_in[2];
    const float* V    = (const float*)d_in[3];
    const int*   src  = (const int*)d_in[4];
    const int*   dst  = (const int*)d_in[5];
    float* out = (float*)d_out;

    int n = in_sizes[1];   // norm has N elements
    int e = in_sizes[4];   // src has E elements
    if (n <= 0) return;

    int G1 = (n + 63) / 64;          // gemm1 blocks (64-row tiles)
    int q  = e >> 2;
    int eb = (q + 255) / 256;        // edge blocks (4 edges/thread)
    if (eb < 1) eb = 1;
    int nb = (n + 1023) / 1024;      // scan blocks (<=128 required by top scan)

    k1_gemm_hist_vt<<<G1 + eb + 8, 256>>>(x, W, V, dst, n, e, G1, eb);
    k_scanAB<<<nb, 1024>>>(n, nb);
    k_scatter<<<eb, 256>>>(src, dst, e);
    k4_agg_gemm2<<<G1, 256>>>(norm, out, n, e);
}